// round 6
// baseline (speedup 1.0000x reference)
#include <cuda_runtime.h>
#include <cuda_bf16.h>
#include <math.h>
#include <stdint.h>

#define BB 4
#define LL 2048
#define DM 1024
#define DI 2048
#define DTR 64
#define M_TOK (BB*LL)           // 8192

typedef __nv_bfloat16 bf16;

// ---------------- scratch (device globals; allocation is forbidden) ----------
__device__ __align__(256) bf16  g_xn_h [M_TOK * DM];
__device__ __align__(256) bf16  g_xn_l [M_TOK * DM];
__device__ __align__(256) float g_xcraw[M_TOK * DI];
__device__ __align__(256) float g_spz  [M_TOK * DI];
__device__ __align__(256) bf16  g_xc_h [M_TOK * DI];
__device__ __align__(256) bf16  g_xc_l [M_TOK * DI];
__device__ __align__(256) bf16  g_dbl_h[M_TOK * DTR];
__device__ __align__(256) bf16  g_dbl_l[M_TOK * DTR];
__device__ __align__(256) unsigned short g_decay16[M_TOK * DI];
__device__ __align__(256) bf16  g_y_h  [M_TOK * DI];
__device__ __align__(256) bf16  g_y_l  [M_TOK * DI];
__device__ __align__(256) bf16  g_t_in [4096*1024];
__device__ __align__(256) bf16  g_t_x  [64*2048];
__device__ __align__(256) bf16  g_t_dt [2048*64];
__device__ __align__(256) bf16  g_t_out[1024*2048];
__device__ __align__(256) float g_scale[4];
__device__ __align__(256) float g_part [4*256];

// ---------------- exact reference math ---------------------------------------
__device__ __forceinline__ float squareplus_f(float x){
    float y = fminf(fmaxf(x*x + 4.0f, 1e-6f), 1e6f);
    float r = (y > 16.0f) ? 0.125f : 0.5f;
    if (y > 64.0f)  r = 0.0625f;
    if (y > 256.0f) r = 0.03125f;
    if (y < 4.0f)   r = 1.0f;
    if (y < 1.0f)   r = 2.0f;
    if (y < 0.25f)  r = 4.0f;
#pragma unroll
    for (int i = 0; i < 3; i++){
        r = r * (1.5f - 0.5f * y * r * r);
        r = fminf(fmaxf(r, 1e-6f), 1e3f);
    }
    float s = fminf(fmaxf(y * r, 0.0f), 1e3f);
    return 0.5f * (x + s);
}

__device__ __forceinline__ unsigned short decay_u16(float z){
    float sg = 0.5f + 0.5f * z / (1.0f + fabsf(z));
    return (unsigned short)(int)rintf(sg * 32768.0f);
}

__device__ __forceinline__ void split_bf(float v, bf16& h, bf16& l){
    h = __float2bfloat16_rn(v);
    l = __float2bfloat16_rn(v - __bfloat162float(h));
}

// ---------------- fused weight scale + quant ----------------------------------
__global__ void k_abs4(const float* __restrict__ W0, const float* __restrict__ W1,
                       const float* __restrict__ W2, const float* __restrict__ W3,
                       int n0, int n1, int n2, int n3, float* __restrict__ partial){
    const float* W; int n;
    if      (blockIdx.y == 0){ W = W0; n = n0; }
    else if (blockIdx.y == 1){ W = W1; n = n1; }
    else if (blockIdx.y == 2){ W = W2; n = n2; }
    else                     { W = W3; n = n3; }
    __shared__ float sm[256];
    float s = 0.0f;
    for (int i = blockIdx.x * 256 + threadIdx.x; i < n; i += gridDim.x * 256){
        float4 v = ((const float4*)W)[i];
        s += fabsf(v.x) + fabsf(v.y) + fabsf(v.z) + fabsf(v.w);
    }
    sm[threadIdx.x] = s; __syncthreads();
    for (int o = 128; o > 0; o >>= 1){
        if (threadIdx.x < o) sm[threadIdx.x] += sm[threadIdx.x + o];
        __syncthreads();
    }
    if (threadIdx.x == 0) partial[blockIdx.y * 256 + blockIdx.x] = sm[0];
}

__global__ void k_absfin4(const float* __restrict__ partial, float i0, float i1,
                          float i2, float i3, float* __restrict__ out){
    __shared__ float sm[256];
    int b = blockIdx.x;
    float invn = (b == 0) ? i0 : (b == 1) ? i1 : (b == 2) ? i2 : i3;
    sm[threadIdx.x] = partial[b * 256 + threadIdx.x]; __syncthreads();
    for (int o = 128; o > 0; o >>= 1){
        if (threadIdx.x < o) sm[threadIdx.x] += sm[threadIdx.x + o];
        __syncthreads();
    }
    if (threadIdx.x == 0) out[b] = sm[0] * invn + 1e-8f;
}

__global__ void k_quant4(const float* __restrict__ W0, const float* __restrict__ W1,
                         const float* __restrict__ W2, const float* __restrict__ W3,
                         bf16* __restrict__ T0, bf16* __restrict__ T1,
                         bf16* __restrict__ T2, bf16* __restrict__ T3,
                         int n0, int n1, int n2, int n3,
                         const float* __restrict__ scale){
    const float* W; bf16* T; int n;
    if      (blockIdx.y == 0){ W = W0; T = T0; n = n0; }
    else if (blockIdx.y == 1){ W = W1; T = T1; n = n1; }
    else if (blockIdx.y == 2){ W = W2; T = T2; n = n2; }
    else                     { W = W3; T = T3; n = n3; }
    float s = scale[blockIdx.y];
    for (int i = blockIdx.x * 256 + threadIdx.x; i < n; i += gridDim.x * 256){
        float4 v = ((const float4*)W)[i];
        float t0 = fminf(fmaxf(rintf(v.x / s), -1.0f), 1.0f);
        float t1 = fminf(fmaxf(rintf(v.y / s), -1.0f), 1.0f);
        float t2 = fminf(fmaxf(rintf(v.z / s), -1.0f), 1.0f);
        float t3 = fminf(fmaxf(rintf(v.w / s), -1.0f), 1.0f);
        __nv_bfloat162 p0 = __floats2bfloat162_rn(t0, t1);
        __nv_bfloat162 p1 = __floats2bfloat162_rn(t2, t3);
        uint2 u; u.x = *(uint32_t*)&p0; u.y = *(uint32_t*)&p1;
        ((uint2*)T)[i] = u;
    }
}

// ---------------- bitshift norm -> hi/lo bf16 ---------------------------------
__global__ void k_norm(const float* __restrict__ x, const float* __restrict__ gamma,
                       const float* __restrict__ step, bf16* __restrict__ xh,
                       bf16* __restrict__ xl){
    __shared__ float sm[256];
    __shared__ float s_mean, s_g;
    int row = blockIdx.x;
    const float4* xr = (const float4*)(x + (size_t)row * DM);
    float4 v = xr[threadIdx.x];
    sm[threadIdx.x] = v.x + v.y + v.z + v.w; __syncthreads();
    for (int o = 128; o > 0; o >>= 1){
        if (threadIdx.x < o) sm[threadIdx.x] += sm[threadIdx.x + o];
        __syncthreads();
    }
    if (threadIdx.x == 0) s_mean = sm[0] * (1.0f / DM);
    __syncthreads();
    float mean = s_mean;
    float cx = v.x - mean, cy = v.y - mean, cz = v.z - mean, cw = v.w - mean;
    sm[threadIdx.x] = cx*cx + cy*cy + cz*cz + cw*cw; __syncthreads();
    for (int o = 128; o > 0; o >>= 1){
        if (threadIdx.x < o) sm[threadIdx.x] += sm[threadIdx.x + o];
        __syncthreads();
    }
    if (threadIdx.x == 0){
        float var = sm[0] * (1.0f / DM);
        float vv = var + 1e-9f;
        float sc = 1.0f;
        if (vv >= 4.0f)     sc = 0.5f;
        if (vv >= 16.0f)    sc = 0.25f;
        if (vv >= 64.0f)    sc = 0.125f;
        if (vv >= 256.0f)   sc = 0.0625f;
        if (vv >= 1024.0f)  sc = 0.03125f;
        if (vv >= 4096.0f)  sc = 0.015625f;
        if (vv >= 16384.0f) sc = 0.0078125f;
        if (vv >= 65536.0f) sc = 0.00390625f;
        if (vv < 1.0f)      sc = 1.0f;
        if (vv < 0.25f)     sc = 2.0f;
        if (vv < 0.0625f)   sc = 4.0f;
        s_g = sc * step[0];
    }
    __syncthreads();
    float g = s_g;
    float4 gm = ((const float4*)gamma)[threadIdx.x];
    float o0 = cx*g*gm.x, o1 = cy*g*gm.y, o2 = cz*g*gm.z, o3 = cw*g*gm.w;
    size_t base = (size_t)row * DM + threadIdx.x * 4;
    bf16 h, l;
    split_bf(o0, h, l); xh[base+0]=h; xl[base+0]=l;
    split_bf(o1, h, l); xh[base+1]=h; xl[base+1]=l;
    split_bf(o2, h, l); xh[base+2]=h; xl[base+2]=l;
    split_bf(o3, h, l); xh[base+3]=h; xl[base+3]=l;
}

// =================== MMA building blocks ======================================
#define RSG 40                    /* padded smem row stride (bf16 elems) */

__device__ __forceinline__ void cp16(uint32_t saddr, const bf16* gptr){
    asm volatile("cp.async.cg.shared.global [%0],[%1],16;\n" :: "r"(saddr), "l"(gptr));
}
__device__ __forceinline__ void ldsm4(uint32_t* r, uint32_t a){
    asm volatile("ldmatrix.sync.aligned.m8n8.x4.shared.b16 {%0,%1,%2,%3},[%4];\n"
        : "=r"(r[0]), "=r"(r[1]), "=r"(r[2]), "=r"(r[3]) : "r"(a));
}
__device__ __forceinline__ void mma16816(float* c, const uint32_t* a, uint32_t b0, uint32_t b1){
    asm volatile(
        "mma.sync.aligned.m16n8k16.row.col.f32.bf16.bf16.f32 "
        "{%0,%1,%2,%3},{%4,%5,%6,%7},{%8,%9},{%0,%1,%2,%3};\n"
        : "+f"(c[0]), "+f"(c[1]), "+f"(c[2]), "+f"(c[3])
        : "r"(a[0]), "r"(a[1]), "r"(a[2]), "r"(a[3]), "r"(b0), "r"(b1));
}

// =================== 512-thread GEMM, tile 128x256 (GEMM1) ====================
// EPI4: split: n<DI -> C0 raw, n>=DI -> C1 = squareplus(v)
__device__ __forceinline__ void ld_stage512(uint32_t sbase, const bf16* __restrict__ Ah,
                                            const bf16* __restrict__ Al,
                                            const bf16* __restrict__ Bw,
                                            int m0, int n0, int K, int kb, int tid){
    constexpr int A_SZ = 128 * RSG;
    int r = tid >> 2, sg = (tid & 3) * 8;
    cp16(sbase + (uint32_t)(r*RSG + sg)*2,        Ah + (size_t)(m0 + r)*K + kb + sg);
    cp16(sbase + (uint32_t)(A_SZ + r*RSG + sg)*2, Al + (size_t)(m0 + r)*K + kb + sg);
#pragma unroll
    for (int j = 0; j < 2; j++){
        int idx = tid + j*512;
        int rb = idx >> 2, sgb = (idx & 3) * 8;
        cp16(sbase + (uint32_t)(2*A_SZ + rb*RSG + sgb)*2, Bw + (size_t)(n0 + rb)*K + kb + sgb);
    }
    asm volatile("cp.async.commit_group;\n" ::);
}

__global__ __launch_bounds__(512, 1)
void k_gemm_512(const bf16* __restrict__ Ah, const bf16* __restrict__ Al,
                const bf16* __restrict__ Bw, int M, int N, int K,
                const float* __restrict__ scale_p,
                float* __restrict__ C0, float* __restrict__ C1){
    constexpr int A_SZ = 128 * RSG;
    constexpr int B_SZ = 256 * RSG;
    constexpr int STG  = 2*A_SZ + B_SZ;
    extern __shared__ __align__(16) bf16 smem[];

    const int tid = threadIdx.x;
    const int m0 = blockIdx.y * 128, n0 = blockIdx.x * 256;
    const int lane = tid & 31, w = tid >> 5;
    const int wm = w & 3, wn = w >> 2;          // 4x4 warp grid
    const int m0w = wm * 32, n0w = wn * 64;

    float acc[2][8][4];
#pragma unroll
    for (int i = 0; i < 2; i++)
#pragma unroll
        for (int j = 0; j < 8; j++)
#pragma unroll
            for (int q = 0; q < 4; q++) acc[i][j][q] = 0.0f;

    const int aoff = (m0w + (lane & 15)) * RSG + (lane >> 4) * 8;
    const int boff = (n0w + ((lane >> 4) << 3) + (lane & 7)) * RSG + ((lane >> 3) & 1) * 8;
    const int NITER = K / 32;
    uint32_t sb = (uint32_t)__cvta_generic_to_shared(smem);

    ld_stage512(sb,         Ah, Al, Bw, m0, n0, K, 0,  tid);
    ld_stage512(sb + STG*2, Ah, Al, Bw, m0, n0, K, 32, tid);

    for (int it = 0; it < NITER; it++){
        if (it + 1 < NITER) asm volatile("cp.async.wait_group 1;\n" ::);
        else                asm volatile("cp.async.wait_group 0;\n" ::);
        __syncthreads();
        if (it + 2 < NITER)
            ld_stage512(sb + (uint32_t)(((it+2)%3)*STG)*2, Ah, Al, Bw, m0, n0, K, (it+2)*32, tid);

        uint32_t sbase = sb + (uint32_t)((it%3)*STG)*2;
#pragma unroll
        for (int ks = 0; ks < 2; ks++){
            int ko = ks * 16;
            uint32_t ah0[4], ah1[4], al0[4], al1[4], bq[4][4];
            ldsm4(ah0, sbase + (uint32_t)(aoff + ko)*2);
            ldsm4(ah1, sbase + (uint32_t)(aoff + 16*RSG + ko)*2);
            ldsm4(al0, sbase + (uint32_t)(A_SZ + aoff + ko)*2);
            ldsm4(al1, sbase + (uint32_t)(A_SZ + aoff + 16*RSG + ko)*2);
#pragma unroll
            for (int j = 0; j < 4; j++)
                ldsm4(bq[j], sbase + (uint32_t)(2*A_SZ + boff + j*16*RSG + ko)*2);
#pragma unroll
            for (int j = 0; j < 4; j++){
                mma16816(acc[0][2*j],   ah0, bq[j][0], bq[j][1]);
                mma16816(acc[0][2*j],   al0, bq[j][0], bq[j][1]);
                mma16816(acc[0][2*j+1], ah0, bq[j][2], bq[j][3]);
                mma16816(acc[0][2*j+1], al0, bq[j][2], bq[j][3]);
                mma16816(acc[1][2*j],   ah1, bq[j][0], bq[j][1]);
                mma16816(acc[1][2*j],   al1, bq[j][0], bq[j][1]);
                mma16816(acc[1][2*j+1], ah1, bq[j][2], bq[j][3]);
                mma16816(acc[1][2*j+1], al1, bq[j][2], bq[j][3]);
            }
        }
    }

    float s = *scale_p;
    bool zhalf = (n0 >= DI);
#pragma unroll
    for (int mt = 0; mt < 2; mt++){
        int r0 = m0 + m0w + mt*16 + (lane >> 2);
        int r1 = r0 + 8;
#pragma unroll
        for (int nt = 0; nt < 8; nt++){
            int c = n0 + n0w + nt*8 + (lane & 3)*2;
            float v0 = acc[mt][nt][0]*s, v1 = acc[mt][nt][1]*s;
            float v2 = acc[mt][nt][2]*s, v3 = acc[mt][nt][3]*s;
            if (!zhalf){
                C0[(size_t)r0*DI + c]   = v0;
                C0[(size_t)r0*DI + c+1] = v1;
                C0[(size_t)r1*DI + c]   = v2;
                C0[(size_t)r1*DI + c+1] = v3;
            } else {
                int cc = c - DI;
                C1[(size_t)r0*DI + cc]   = squareplus_f(v0);
                C1[(size_t)r0*DI + cc+1] = squareplus_f(v1);
                C1[(size_t)r1*DI + cc]   = squareplus_f(v2);
                C1[(size_t)r1*DI + cc+1] = squareplus_f(v3);
            }
        }
    }
}

// =================== 256-thread HMMA GEMM (other GEMMs) =======================
template<int BN>
__device__ __forceinline__ void ld_stage(uint32_t sbase, const bf16* __restrict__ Ah,
                                         const bf16* __restrict__ Al,
                                         const bf16* __restrict__ Bw,
                                         int m0, int n0, int K, int kb, int tid){
    constexpr int A_SZ = 128 * RSG;
#pragma unroll
    for (int j = 0; j < 2; j++){
        int idx = tid + j*256;
        int r = idx >> 2, sg = (idx & 3) * 8;
        cp16(sbase + (uint32_t)(r*RSG + sg)*2, Ah + (size_t)(m0 + r)*K + kb + sg);
    }
#pragma unroll
    for (int j = 0; j < 2; j++){
        int idx = tid + j*256;
        int r = idx >> 2, sg = (idx & 3) * 8;
        cp16(sbase + (uint32_t)(A_SZ + r*RSG + sg)*2, Al + (size_t)(m0 + r)*K + kb + sg);
    }
#pragma unroll
    for (int j = 0; j < BN*4/256; j++){
        int idx = tid + j*256;
        int r = idx >> 2, sg = (idx & 3) * 8;
        cp16(sbase + (uint32_t)(2*A_SZ + r*RSG + sg)*2, Bw + (size_t)(n0 + r)*K + kb + sg);
    }
    asm volatile("cp.async.commit_group;\n" ::);
}

// EPI: 1 decay->u16 | 2 +resid->C0 | 3 hi/lo bf16 -> H0,H1
template<int BN, int EPI>
__global__ __launch_bounds__(256, 2)
void k_gemm_bf(const bf16* __restrict__ Ah, const bf16* __restrict__ Al,
               const bf16* __restrict__ Bw, int M, int N, int K,
               const float* __restrict__ scale_p,
               const float* __restrict__ bias,
               const float* __restrict__ resid,
               float* __restrict__ C0,
               bf16* __restrict__ H0, bf16* __restrict__ H1,
               unsigned short* __restrict__ U16){
    constexpr int A_SZ = 128 * RSG;
    constexpr int B_SZ = BN * RSG;
    constexpr int STG  = 2*A_SZ + B_SZ;
    constexpr int NG = BN / 32;
    constexpr int NT = BN / 16;
    extern __shared__ __align__(16) bf16 smem[];

    const int tid = threadIdx.x;
    const int m0 = blockIdx.y * 128, n0 = blockIdx.x * BN;
    const int lane = tid & 31, w = tid >> 5;
    const int wm = w >> 1, wn = w & 1;
    const int m0w = wm * 32, n0w = wn * (BN/2);

    float acc[2][NT][4];
#pragma unroll
    for (int i = 0; i < 2; i++)
#pragma unroll
        for (int j = 0; j < NT; j++)
#pragma unroll
            for (int q = 0; q < 4; q++) acc[i][j][q] = 0.0f;

    const int aoff = (m0w + (lane & 15)) * RSG + (lane >> 4) * 8;
    const int boff = (n0w + ((lane >> 4) << 3) + (lane & 7)) * RSG + ((lane >> 3) & 1) * 8;
    const int NITER = K / 32;
    uint32_t sb = (uint32_t)__cvta_generic_to_shared(smem);

    ld_stage<BN>(sb,         Ah, Al, Bw, m0, n0, K, 0,  tid);
    ld_stage<BN>(sb + STG*2, Ah, Al, Bw, m0, n0, K, 32, tid);

    for (int it = 0; it < NITER; it++){
        if (it + 1 < NITER) asm volatile("cp.async.wait_group 1;\n" ::);
        else                asm volatile("cp.async.wait_group 0;\n" ::);
        __syncthreads();
        if (it + 2 < NITER)
            ld_stage<BN>(sb + (uint32_t)(((it+2)%3)*STG)*2, Ah, Al, Bw, m0, n0, K, (it+2)*32, tid);

        uint32_t sbase = sb + (uint32_t)((it%3)*STG)*2;
#pragma unroll
        for (int ks = 0; ks < 2; ks++){
            int ko = ks * 16;
            uint32_t ah0[4], ah1[4], al0[4], al1[4], bq[NG][4];
            ldsm4(ah0, sbase + (uint32_t)(aoff + ko)*2);
            ldsm4(ah1, sbase + (uint32_t)(aoff + 16*RSG + ko)*2);
            ldsm4(al0, sbase + (uint32_t)(A_SZ + aoff + ko)*2);
            ldsm4(al1, sbase + (uint32_t)(A_SZ + aoff + 16*RSG + ko)*2);
#pragma unroll
            for (int j = 0; j < NG; j++)
                ldsm4(bq[j], sbase + (uint32_t)(2*A_SZ + boff + j*16*RSG + ko)*2);
#pragma unroll
            for (int j = 0; j < NG; j++){
                mma16816(acc[0][2*j],   ah0, bq[j][0], bq[j][1]);
                mma16816(acc[0][2*j],   al0, bq[j][0], bq[j][1]);
                mma16816(acc[0][2*j+1], ah0, bq[j][2], bq[j][3]);
                mma16816(acc[0][2*j+1], al0, bq[j][2], bq[j][3]);
                mma16816(acc[1][2*j],   ah1, bq[j][0], bq[j][1]);
                mma16816(acc[1][2*j],   al1, bq[j][0], bq[j][1]);
                mma16816(acc[1][2*j+1], ah1, bq[j][2], bq[j][3]);
                mma16816(acc[1][2*j+1], al1, bq[j][2], bq[j][3]);
            }
        }
    }

    float s = *scale_p;
#pragma unroll
    for (int mt = 0; mt < 2; mt++){
        int r0 = m0 + m0w + mt*16 + (lane >> 2);
        int r1 = r0 + 8;
#pragma unroll
        for (int nt = 0; nt < NT; nt++){
            int c = n0 + n0w + nt*8 + (lane & 3)*2;
            float v0 = acc[mt][nt][0]*s, v1 = acc[mt][nt][1]*s;
            float v2 = acc[mt][nt][2]*s, v3 = acc[mt][nt][3]*s;
            if (EPI == 1){
                U16[(size_t)r0*N + c]   = decay_u16(v0 + bias[c]);
                U16[(size_t)r0*N + c+1] = decay_u16(v1 + bias[c+1]);
                U16[(size_t)r1*N + c]   = decay_u16(v2 + bias[c]);
                U16[(size_t)r1*N + c+1] = decay_u16(v3 + bias[c+1]);
            } else if (EPI == 2){
                C0[(size_t)r0*N + c]   = v0 + resid[(size_t)r0*N + c];
                C0[(size_t)r0*N + c+1] = v1 + resid[(size_t)r0*N + c+1];
                C0[(size_t)r1*N + c]   = v2 + resid[(size_t)r1*N + c];
                C0[(size_t)r1*N + c+1] = v3 + resid[(size_t)r1*N + c+1];
            } else {
                bf16 h, l;
                split_bf(v0, h, l); H0[(size_t)r0*N + c]   = h; H1[(size_t)r0*N + c]   = l;
                split_bf(v1, h, l); H0[(size_t)r0*N + c+1] = h; H1[(size_t)r0*N + c+1] = l;
                split_bf(v2, h, l); H0[(size_t)r1*N + c]   = h; H1[(size_t)r1*N + c]   = l;
                split_bf(v3, h, l); H0[(size_t)r1*N + c+1] = h; H1[(size_t)r1*N + c+1] = l;
            }
        }
    }
}

// ---------------- causal depthwise conv1d(k=4) + squareplus (x4 vector) ------
__global__ void k_conv(const float* __restrict__ xcraw, const float* __restrict__ cw,
                       const float* __restrict__ cb, bf16* __restrict__ xh,
                       bf16* __restrict__ xl){
    int i = blockIdx.x * 256 + threadIdx.x;
    int idx = i * 4;
    int dv = (idx & (DI - 1)) >> 2;
    int m = idx >> 11;
    int t = m & (LL - 1);
    const float4* x4 = (const float4*)xcraw;
    float4 xt = x4[i];
    float4 z = make_float4(0.f,0.f,0.f,0.f);
    float4 x1 = (t >= 1) ? x4[i - DI/4]   : z;
    float4 x2 = (t >= 2) ? x4[i - 2*DI/4] : z;
    float4 x3 = (t >= 3) ? x4[i - 3*DI/4] : z;
    const float4* cw4 = (const float4*)cw;
    int d0 = dv * 4;
    float4 wa = cw4[d0+0], wb = cw4[d0+1], wc = cw4[d0+2], wd = cw4[d0+3];
    float4 cbv = ((const float4*)cb)[dv];
    float s0 = cbv.x + wa.w*xt.x + wa.z*x1.x + wa.y*x2.x + wa.x*x3.x;
    float s1 = cbv.y + wb.w*xt.y + wb.z*x1.y + wb.y*x2.y + wb.x*x3.y;
    float s2 = cbv.z + wc.w*xt.z + wc.z*x1.z + wc.y*x2.z + wc.x*x3.z;
    float s3 = cbv.w + wd.w*xt.w + wd.z*x1.w + wd.y*x2.w + wd.x*x3.w;
    float v0 = squareplus_f(s0), v1 = squareplus_f(s1);
    float v2 = squareplus_f(s2), v3 = squareplus_f(s3);
    bf16 h0,l0,h1,l1,h2,l2,h3,l3;
    split_bf(v0,h0,l0); split_bf(v1,h1,l1); split_bf(v2,h2,l2); split_bf(v3,h3,l3);
    __nv_bfloat162 ph0 = __nv_bfloat162(h0,h1), ph1 = __nv_bfloat162(h2,h3);
    __nv_bfloat162 pl0 = __nv_bfloat162(l0,l1), pl1 = __nv_bfloat162(l2,l3);
    uint2 uh; uh.x = *(uint32_t*)&ph0; uh.y = *(uint32_t*)&ph1;
    uint2 ul; ul.x = *(uint32_t*)&pl0; ul.y = *(uint32_t*)&pl1;
    ((uint2*)xh)[i] = uh;
    ((uint2*)xl)[i] = ul;
}

// ---------------- chunked scan (32 slices x 64 steps) + fused y --------------
__global__ void k_scan(const bf16* __restrict__ uh, const bf16* __restrict__ ul,
                       const unsigned short* __restrict__ a16,
                       const float* __restrict__ spz,
                       bf16* __restrict__ yh, bf16* __restrict__ yl){
    const int c = blockIdx.x * 32 + threadIdx.x;
    const int b = blockIdx.y;
    const int slice = threadIdx.y;
    const int CH = LL / 32;
    size_t base = ((size_t)b * LL) * DI + c;
    int t0 = slice * CH;

    float A = 1.0f, Bv = 0.0f;
    size_t idx = base + (size_t)t0 * DI;
    for (int t = 0; t < CH; t++, idx += DI){
        float at = (float)a16[idx] * (1.0f/32768.0f);
        float ut = __bfloat162float(uh[idx]) + __bfloat162float(ul[idx]);
        Bv = at * Bv + (1.0f - at) * ut;
        A *= at;
    }
    __shared__ float sA[32][32], sB[32][32], sP[32][32];
    sA[slice][threadIdx.x] = A;
    sB[slice][threadIdx.x] = Bv;
    __syncthreads();
    if (slice == 0){
        float carry = 0.0f;
#pragma unroll
        for (int s2 = 0; s2 < 32; s2++){
            sP[s2][threadIdx.x] = carry;
            carry = sA[s2][threadIdx.x] * carry + sB[s2][threadIdx.x];
        }
    }
    __syncthreads();
    float h = sP[slice][threadIdx.x];
    idx = base + (size_t)t0 * DI;
    for (int t = 0; t < CH; t++, idx += DI){
        float at = (float)a16[idx] * (1.0f/32768.0f);
        float ut = __bfloat162float(uh[idx]) + __bfloat162float(ul[idx]);
        h = at * h + (1.0f - at) * ut;
        float y = h * spz[idx];
        bf16 hh, llv; split_bf(y, hh, llv);
        yh[idx] = hh; yl[idx] = llv;
    }
}

// ---------------- launch ------------------------------------------------------
extern "C" void kernel_launch(void* const* d_in, const int* in_sizes, int n_in,
                              void* d_out, int out_size){
    const float* x     = (const float*)d_in[0];
    const float* gamma = (const float*)d_in[1];
    const float* step  = (const float*)d_in[2];
    const float* W_in  = (const float*)d_in[3];
    const float* cw    = (const float*)d_in[4];
    const float* cb    = (const float*)d_in[5];
    const float* W_x   = (const float*)d_in[6];
    const float* W_dt  = (const float*)d_in[7];
    const float* b_dt  = (const float*)d_in[8];
    const float* W_out = (const float*)d_in[9];
    float* out = (float*)d_out;

    bf16 *p_xnh, *p_xnl, *p_xch, *p_xcl, *p_dblh, *p_dbll, *p_yh, *p_yl;
    bf16 *p_tin, *p_tx, *p_tdt, *p_tout;
    float *p_xcraw, *p_spz, *p_scale, *p_part;
    unsigned short* p_decay;
    cudaGetSymbolAddress((void**)&p_xnh,   g_xn_h);
    cudaGetSymbolAddress((void**)&p_xnl,   g_xn_l);
    cudaGetSymbolAddress((void**)&p_xcraw, g_xcraw);
    cudaGetSymbolAddress((void**)&p_spz,   g_spz);
    cudaGetSymbolAddress((void**)&p_xch,   g_xc_h);
    cudaGetSymbolAddress((void**)&p_xcl,   g_xc_l);
    cudaGetSymbolAddress((void**)&p_dblh,  g_dbl_h);
    cudaGetSymbolAddress((void**)&p_dbll,  g_dbl_l);
    cudaGetSymbolAddress((void**)&p_decay, g_decay16);
    cudaGetSymbolAddress((void**)&p_yh,    g_y_h);
    cudaGetSymbolAddress((void**)&p_yl,    g_y_l);
    cudaGetSymbolAddress((void**)&p_tin,   g_t_in);
    cudaGetSymbolAddress((void**)&p_tx,    g_t_x);
    cudaGetSymbolAddress((void**)&p_tdt,   g_t_dt);
    cudaGetSymbolAddress((void**)&p_tout,  g_t_out);
    cudaGetSymbolAddress((void**)&p_scale, g_scale);
    cudaGetSymbolAddress((void**)&p_part,  g_part);

    const int SM512 = 3*(2*128*RSG + 256*RSG)*2;   // 122880
    const int SM64  = 3*(2*128*RSG +  64*RSG)*2;
    const int SM128 = 3*(2*128*RSG + 128*RSG)*2;
    cudaFuncSetAttribute(k_gemm_512, cudaFuncAttributeMaxDynamicSharedMemorySize, SM512);
    cudaFuncSetAttribute(k_gemm_bf<64,3>,  cudaFuncAttributeMaxDynamicSharedMemorySize, SM64);
    cudaFuncSetAttribute(k_gemm_bf<128,1>, cudaFuncAttributeMaxDynamicSharedMemorySize, SM128);
    cudaFuncSetAttribute(k_gemm_bf<128,2>, cudaFuncAttributeMaxDynamicSharedMemorySize, SM128);

    // 1) ternary scales + exact-ternary bf16 weights (fused launches)
    k_abs4<<<dim3(256,4),256>>>(W_in, W_x, W_dt, W_out,
                                4096*1024/4, 96*2048/4, 2048*64/4, 1024*2048/4, p_part);
    k_absfin4<<<4,256>>>(p_part, 1.0f/4194304.0f, 1.0f/196608.0f,
                         1.0f/131072.0f, 1.0f/2097152.0f, p_scale);
    k_quant4<<<dim3(1024,4),256>>>(W_in, W_x, W_dt, W_out,
                                   p_tin, p_tx, p_tdt, p_tout,
                                   4194304/4, 131072/4, 131072/4, 2097152/4, p_scale);

    // 2) norm -> hi/lo bf16
    k_norm<<<M_TOK,256>>>(x, gamma, step, p_xnh, p_xnl);

    // 3) in-projection (512-thread 128x256 tiles): split xc_raw | squareplus(z)
    k_gemm_512<<<dim3(16,64),512,SM512>>>(p_xnh, p_xnl, p_tin, M_TOK, 4096, 1024,
                                          p_scale+0, p_xcraw, p_spz);

    // 4) causal conv + squareplus -> xc hi/lo
    k_conv<<<M_TOK*DI/4/256,256>>>(p_xcraw, cw, cb, p_xch, p_xcl);

    // 5) dt_rank projection -> dbl hi/lo
    k_gemm_bf<64,3><<<dim3(1,64),256,SM64>>>(p_xch, p_xcl, p_tx, M_TOK, 64, 2048,
                                             p_scale+1, nullptr, nullptr, nullptr,
                                             p_dblh, p_dbll, nullptr);

    // 6) dt projection + fused sigmoid + dyadic round -> decay u16
    k_gemm_bf<128,1><<<dim3(16,64),256,SM128>>>(p_dblh, p_dbll, p_tdt, M_TOK, 2048, 64,
                                                p_scale+2, b_dt, nullptr, nullptr,
                                                nullptr, nullptr, p_decay);

    // 7) scan + fused y = h * spz -> hi/lo
    k_scan<<<dim3(DI/32, BB), dim3(32,32)>>>(p_xch, p_xcl, p_decay, p_spz, p_yh, p_yl);

    // 8) out-projection + residual -> d_out
    k_gemm_bf<128,2><<<dim3(8,64),256,SM128>>>(p_yh, p_yl, p_tout, M_TOK, 1024, 2048,
                                               p_scale+3, nullptr, x, out,
                                               nullptr, nullptr, nullptr);
}

// round 7
// speedup vs baseline: 1.5862x; 1.5862x over previous
#include <cuda_runtime.h>
#include <cuda_fp16.h>
#include <math.h>
#include <stdint.h>

#define BB 4
#define LL 2048
#define DM 1024
#define DI 2048
#define DTR 64
#define M_TOK (BB*LL)           // 8192

// ---------------- scratch (device globals; allocation is forbidden) ----------
__device__ __align__(256) __half g_xn   [M_TOK * DM];
__device__ __align__(256) float  g_xcraw[M_TOK * DI];
__device__ __align__(256) float  g_spz  [M_TOK * DI];
__device__ __align__(256) __half g_u    [M_TOK * DI];
__device__ __align__(256) __half g_dbl  [M_TOK * DTR];
__device__ __align__(256) unsigned short g_decay16[M_TOK * DI];
__device__ __align__(256) __half g_y    [M_TOK * DI];
__device__ __align__(256) __half g_t_in [4096*1024];
__device__ __align__(256) __half g_t_x  [64*2048];
__device__ __align__(256) __half g_t_dt [2048*64];
__device__ __align__(256) __half g_t_out[1024*2048];
__device__ __align__(256) float  g_scale[4];
__device__ __align__(256) float  g_part [4*256];

// ---------------- exact reference math ---------------------------------------
__device__ __forceinline__ float squareplus_f(float x){
    float y = fminf(fmaxf(x*x + 4.0f, 1e-6f), 1e6f);
    float r = (y > 16.0f) ? 0.125f : 0.5f;
    if (y > 64.0f)  r = 0.0625f;
    if (y > 256.0f) r = 0.03125f;
    if (y < 4.0f)   r = 1.0f;
    if (y < 1.0f)   r = 2.0f;
    if (y < 0.25f)  r = 4.0f;
#pragma unroll
    for (int i = 0; i < 3; i++){
        r = r * (1.5f - 0.5f * y * r * r);
        r = fminf(fmaxf(r, 1e-6f), 1e3f);
    }
    float s = fminf(fmaxf(y * r, 0.0f), 1e3f);
    return 0.5f * (x + s);
}

__device__ __forceinline__ unsigned short decay_u16(float z){
    float sg = 0.5f + 0.5f * z / (1.0f + fabsf(z));
    return (unsigned short)(int)rintf(sg * 32768.0f);
}

// ---------------- fused weight scale + quant ----------------------------------
__global__ void k_abs4(const float* __restrict__ W0, const float* __restrict__ W1,
                       const float* __restrict__ W2, const float* __restrict__ W3,
                       int n0, int n1, int n2, int n3, float* __restrict__ partial){
    const float* W; int n;
    if      (blockIdx.y == 0){ W = W0; n = n0; }
    else if (blockIdx.y == 1){ W = W1; n = n1; }
    else if (blockIdx.y == 2){ W = W2; n = n2; }
    else                     { W = W3; n = n3; }
    __shared__ float sm[256];
    float s = 0.0f;
    for (int i = blockIdx.x * 256 + threadIdx.x; i < n; i += gridDim.x * 256){
        float4 v = ((const float4*)W)[i];
        s += fabsf(v.x) + fabsf(v.y) + fabsf(v.z) + fabsf(v.w);
    }
    sm[threadIdx.x] = s; __syncthreads();
    for (int o = 128; o > 0; o >>= 1){
        if (threadIdx.x < o) sm[threadIdx.x] += sm[threadIdx.x + o];
        __syncthreads();
    }
    if (threadIdx.x == 0) partial[blockIdx.y * 256 + blockIdx.x] = sm[0];
}

__global__ void k_absfin4(const float* __restrict__ partial, float i0, float i1,
                          float i2, float i3, float* __restrict__ out){
    __shared__ float sm[256];
    int b = blockIdx.x;
    float invn = (b == 0) ? i0 : (b == 1) ? i1 : (b == 2) ? i2 : i3;
    sm[threadIdx.x] = partial[b * 256 + threadIdx.x]; __syncthreads();
    for (int o = 128; o > 0; o >>= 1){
        if (threadIdx.x < o) sm[threadIdx.x] += sm[threadIdx.x + o];
        __syncthreads();
    }
    if (threadIdx.x == 0) out[b] = sm[0] * invn + 1e-8f;
}

__global__ void k_quant4(const float* __restrict__ W0, const float* __restrict__ W1,
                         const float* __restrict__ W2, const float* __restrict__ W3,
                         __half* __restrict__ T0, __half* __restrict__ T1,
                         __half* __restrict__ T2, __half* __restrict__ T3,
                         int n0, int n1, int n2, int n3,
                         const float* __restrict__ scale){
    const float* W; __half* T; int n;
    if      (blockIdx.y == 0){ W = W0; T = T0; n = n0; }
    else if (blockIdx.y == 1){ W = W1; T = T1; n = n1; }
    else if (blockIdx.y == 2){ W = W2; T = T2; n = n2; }
    else                     { W = W3; T = T3; n = n3; }
    float s = scale[blockIdx.y];
    for (int i = blockIdx.x * 256 + threadIdx.x; i < n; i += gridDim.x * 256){
        float4 v = ((const float4*)W)[i];
        float t0 = fminf(fmaxf(rintf(v.x / s), -1.0f), 1.0f);
        float t1 = fminf(fmaxf(rintf(v.y / s), -1.0f), 1.0f);
        float t2 = fminf(fmaxf(rintf(v.z / s), -1.0f), 1.0f);
        float t3 = fminf(fmaxf(rintf(v.w / s), -1.0f), 1.0f);
        __half2 p0 = __floats2half2_rn(t0, t1);
        __half2 p1 = __floats2half2_rn(t2, t3);
        uint2 u; u.x = *(uint32_t*)&p0; u.y = *(uint32_t*)&p1;
        ((uint2*)T)[i] = u;
    }
}

// ---------------- bitshift norm -> fp16 (packed stores) -----------------------
__global__ void k_norm(const float* __restrict__ x, const float* __restrict__ gamma,
                       const float* __restrict__ step, __half* __restrict__ xn){
    __shared__ float sm[256];
    __shared__ float s_mean, s_g;
    int row = blockIdx.x;
    const float4* xr = (const float4*)(x + (size_t)row * DM);
    float4 v = xr[threadIdx.x];
    sm[threadIdx.x] = v.x + v.y + v.z + v.w; __syncthreads();
    for (int o = 128; o > 0; o >>= 1){
        if (threadIdx.x < o) sm[threadIdx.x] += sm[threadIdx.x + o];
        __syncthreads();
    }
    if (threadIdx.x == 0) s_mean = sm[0] * (1.0f / DM);
    __syncthreads();
    float mean = s_mean;
    float cx = v.x - mean, cy = v.y - mean, cz = v.z - mean, cw = v.w - mean;
    sm[threadIdx.x] = cx*cx + cy*cy + cz*cz + cw*cw; __syncthreads();
    for (int o = 128; o > 0; o >>= 1){
        if (threadIdx.x < o) sm[threadIdx.x] += sm[threadIdx.x + o];
        __syncthreads();
    }
    if (threadIdx.x == 0){
        float var = sm[0] * (1.0f / DM);
        float vv = var + 1e-9f;
        float sc = 1.0f;
        if (vv >= 4.0f)     sc = 0.5f;
        if (vv >= 16.0f)    sc = 0.25f;
        if (vv >= 64.0f)    sc = 0.125f;
        if (vv >= 256.0f)   sc = 0.0625f;
        if (vv >= 1024.0f)  sc = 0.03125f;
        if (vv >= 4096.0f)  sc = 0.015625f;
        if (vv >= 16384.0f) sc = 0.0078125f;
        if (vv >= 65536.0f) sc = 0.00390625f;
        if (vv < 1.0f)      sc = 1.0f;
        if (vv < 0.25f)     sc = 2.0f;
        if (vv < 0.0625f)   sc = 4.0f;
        s_g = sc * step[0];
    }
    __syncthreads();
    float g = s_g;
    float4 gm = ((const float4*)gamma)[threadIdx.x];
    __half2 p0 = __floats2half2_rn(cx*g*gm.x, cy*g*gm.y);
    __half2 p1 = __floats2half2_rn(cz*g*gm.z, cw*g*gm.w);
    uint2 uu; uu.x = *(uint32_t*)&p0; uu.y = *(uint32_t*)&p1;
    ((uint2*)xn)[ (size_t)row * (DM/4) + threadIdx.x ] = uu;
}

// =================== MMA building blocks ======================================
#define RSG 40                    /* padded smem row stride (half elems) */

__device__ __forceinline__ void cp16(uint32_t saddr, const void* gptr){
    asm volatile("cp.async.cg.shared.global [%0],[%1],16;\n" :: "r"(saddr), "l"(gptr));
}
__device__ __forceinline__ void ldsm4(uint32_t* r, uint32_t a){
    asm volatile("ldmatrix.sync.aligned.m8n8.x4.shared.b16 {%0,%1,%2,%3},[%4];\n"
        : "=r"(r[0]), "=r"(r[1]), "=r"(r[2]), "=r"(r[3]) : "r"(a));
}
__device__ __forceinline__ void mma16816(float* c, const uint32_t* a, uint32_t b0, uint32_t b1){
    asm volatile(
        "mma.sync.aligned.m16n8k16.row.col.f32.f16.f16.f32 "
        "{%0,%1,%2,%3},{%4,%5,%6,%7},{%8,%9},{%0,%1,%2,%3};\n"
        : "+f"(c[0]), "+f"(c[1]), "+f"(c[2]), "+f"(c[3])
        : "r"(a[0]), "r"(a[1]), "r"(a[2]), "r"(a[3]), "r"(b0), "r"(b1));
}

// =================== single-A fp16 GEMM, 256 threads, BK=32, 3 stages ========
template<int BN>
__device__ __forceinline__ void ld_stage(uint32_t sbase, const __half* __restrict__ A,
                                         const __half* __restrict__ Bw,
                                         int m0, int n0, int K, int kb, int tid){
    constexpr int A_SZ = 128 * RSG;
#pragma unroll
    for (int j = 0; j < 2; j++){
        int idx = tid + j*256;
        int r = idx >> 2, sg = (idx & 3) * 8;
        cp16(sbase + (uint32_t)(r*RSG + sg)*2, A + (size_t)(m0 + r)*K + kb + sg);
    }
#pragma unroll
    for (int j = 0; j < BN*4/256; j++){
        int idx = tid + j*256;
        int r = idx >> 2, sg = (idx & 3) * 8;
        cp16(sbase + (uint32_t)(A_SZ + r*RSG + sg)*2, Bw + (size_t)(n0 + r)*K + kb + sg);
    }
    asm volatile("cp.async.commit_group;\n" ::);
}

// EPI: 1 decay->u16 | 2 +resid->C0 | 3 fp16 -> H0 | 4 split xcraw|spz
template<int BN, int EPI>
__global__ __launch_bounds__(256, 2)
void k_gemm_h(const __half* __restrict__ A, const __half* __restrict__ Bw,
              int M, int N, int K,
              const float* __restrict__ scale_p,
              const float* __restrict__ bias,
              const float* __restrict__ resid,
              float* __restrict__ C0, float* __restrict__ C1,
              __half* __restrict__ H0,
              unsigned short* __restrict__ U16){
    constexpr int A_SZ = 128 * RSG;
    constexpr int B_SZ = BN * RSG;
    constexpr int STG  = A_SZ + B_SZ;
    constexpr int NG = BN / 32;
    constexpr int NT = BN / 16;
    extern __shared__ __align__(16) __half smem[];

    const int tid = threadIdx.x;
    const int m0 = blockIdx.y * 128, n0 = blockIdx.x * BN;
    const int lane = tid & 31, w = tid >> 5;
    const int wm = w >> 1, wn = w & 1;
    const int m0w = wm * 32, n0w = wn * (BN/2);

    float acc[2][NT][4];
#pragma unroll
    for (int i = 0; i < 2; i++)
#pragma unroll
        for (int j = 0; j < NT; j++)
#pragma unroll
            for (int q = 0; q < 4; q++) acc[i][j][q] = 0.0f;

    const int aoff = (m0w + (lane & 15)) * RSG + (lane >> 4) * 8;
    const int boff = (n0w + ((lane >> 4) << 3) + (lane & 7)) * RSG + ((lane >> 3) & 1) * 8;
    const int NITER = K / 32;
    uint32_t sb = (uint32_t)__cvta_generic_to_shared(smem);

    ld_stage<BN>(sb,         A, Bw, m0, n0, K, 0,  tid);
    ld_stage<BN>(sb + STG*2, A, Bw, m0, n0, K, 32, tid);

    for (int it = 0; it < NITER; it++){
        if (it + 1 < NITER) asm volatile("cp.async.wait_group 1;\n" ::);
        else                asm volatile("cp.async.wait_group 0;\n" ::);
        __syncthreads();
        if (it + 2 < NITER)
            ld_stage<BN>(sb + (uint32_t)(((it+2)%3)*STG)*2, A, Bw, m0, n0, K, (it+2)*32, tid);

        uint32_t sbase = sb + (uint32_t)((it%3)*STG)*2;
#pragma unroll
        for (int ks = 0; ks < 2; ks++){
            int ko = ks * 16;
            uint32_t ah0[4], ah1[4], bq[NG][4];
            ldsm4(ah0, sbase + (uint32_t)(aoff + ko)*2);
            ldsm4(ah1, sbase + (uint32_t)(aoff + 16*RSG + ko)*2);
#pragma unroll
            for (int j = 0; j < NG; j++)
                ldsm4(bq[j], sbase + (uint32_t)(A_SZ + boff + j*16*RSG + ko)*2);
#pragma unroll
            for (int j = 0; j < NG; j++){
                mma16816(acc[0][2*j],   ah0, bq[j][0], bq[j][1]);
                mma16816(acc[0][2*j+1], ah0, bq[j][2], bq[j][3]);
                mma16816(acc[1][2*j],   ah1, bq[j][0], bq[j][1]);
                mma16816(acc[1][2*j+1], ah1, bq[j][2], bq[j][3]);
            }
        }
    }

    float s = *scale_p;
#pragma unroll
    for (int mt = 0; mt < 2; mt++){
        int r0 = m0 + m0w + mt*16 + (lane >> 2);
        int r1 = r0 + 8;
#pragma unroll
        for (int nt = 0; nt < NT; nt++){
            int c = n0 + n0w + nt*8 + (lane & 3)*2;
            float v0 = acc[mt][nt][0]*s, v1 = acc[mt][nt][1]*s;
            float v2 = acc[mt][nt][2]*s, v3 = acc[mt][nt][3]*s;
            if (EPI == 1){
                U16[(size_t)r0*N + c]   = decay_u16(v0 + bias[c]);
                U16[(size_t)r0*N + c+1] = decay_u16(v1 + bias[c+1]);
                U16[(size_t)r1*N + c]   = decay_u16(v2 + bias[c]);
                U16[(size_t)r1*N + c+1] = decay_u16(v3 + bias[c+1]);
            } else if (EPI == 2){
                C0[(size_t)r0*N + c]   = v0 + resid[(size_t)r0*N + c];
                C0[(size_t)r0*N + c+1] = v1 + resid[(size_t)r0*N + c+1];
                C0[(size_t)r1*N + c]   = v2 + resid[(size_t)r1*N + c];
                C0[(size_t)r1*N + c+1] = v3 + resid[(size_t)r1*N + c+1];
            } else if (EPI == 3){
                __half2 p0 = __floats2half2_rn(v0, v1);
                __half2 p1 = __floats2half2_rn(v2, v3);
                *(uint32_t*)&H0[(size_t)r0*N + c] = *(uint32_t*)&p0;
                *(uint32_t*)&H0[(size_t)r1*N + c] = *(uint32_t*)&p1;
            } else {  // EPI == 4
                if (c < DI){
                    C0[(size_t)r0*DI + c]   = v0;
                    C0[(size_t)r0*DI + c+1] = v1;
                    C0[(size_t)r1*DI + c]   = v2;
                    C0[(size_t)r1*DI + c+1] = v3;
                } else {
                    int cc = c - DI;
                    C1[(size_t)r0*DI + cc]   = squareplus_f(v0);
                    C1[(size_t)r0*DI + cc+1] = squareplus_f(v1);
                    C1[(size_t)r1*DI + cc]   = squareplus_f(v2);
                    C1[(size_t)r1*DI + cc+1] = squareplus_f(v3);
                }
            }
        }
    }
}

// ---------------- causal depthwise conv1d(k=4) + squareplus -> fp16 ----------
__global__ void k_conv(const float* __restrict__ xcraw, const float* __restrict__ cw,
                       const float* __restrict__ cb, __half* __restrict__ u){
    int i = blockIdx.x * 256 + threadIdx.x;
    int idx = i * 4;
    int dv = (idx & (DI - 1)) >> 2;
    int m = idx >> 11;
    int t = m & (LL - 1);
    const float4* x4 = (const float4*)xcraw;
    float4 xt = x4[i];
    float4 z = make_float4(0.f,0.f,0.f,0.f);
    float4 x1 = (t >= 1) ? x4[i - DI/4]   : z;
    float4 x2 = (t >= 2) ? x4[i - 2*DI/4] : z;
    float4 x3 = (t >= 3) ? x4[i - 3*DI/4] : z;
    const float4* cw4 = (const float4*)cw;
    int d0 = dv * 4;
    float4 wa = cw4[d0+0], wb = cw4[d0+1], wc = cw4[d0+2], wd = cw4[d0+3];
    float4 cbv = ((const float4*)cb)[dv];
    float s0 = cbv.x + wa.w*xt.x + wa.z*x1.x + wa.y*x2.x + wa.x*x3.x;
    float s1 = cbv.y + wb.w*xt.y + wb.z*x1.y + wb.y*x2.y + wb.x*x3.y;
    float s2 = cbv.z + wc.w*xt.z + wc.z*x1.z + wc.y*x2.z + wc.x*x3.z;
    float s3 = cbv.w + wd.w*xt.w + wd.z*x1.w + wd.y*x2.w + wd.x*x3.w;
    __half2 p0 = __floats2half2_rn(squareplus_f(s0), squareplus_f(s1));
    __half2 p1 = __floats2half2_rn(squareplus_f(s2), squareplus_f(s3));
    uint2 uu; uu.x = *(uint32_t*)&p0; uu.y = *(uint32_t*)&p1;
    ((uint2*)u)[i] = uu;
}

// ---------------- chunked scan, 2 channels/thread, 32 slices x 64 ------------
__global__ void k_scan(const __half* __restrict__ u,
                       const unsigned short* __restrict__ a16,
                       const float* __restrict__ spz,
                       __half* __restrict__ y){
    const int tx = threadIdx.x;
    const int c0 = (blockIdx.x * 32 + tx) * 2;
    const int b = blockIdx.y;
    const int slice = threadIdx.y;
    const int CH = LL / 32;                        // 64
    size_t base = ((size_t)b * LL) * DI + c0;
    int t0 = slice * CH;

    float A0 = 1.0f, B0 = 0.0f, A1 = 1.0f, B1 = 0.0f;
    size_t idx = base + (size_t)t0 * DI;
    for (int t = 0; t < CH; t++, idx += DI){
        uint32_t aa = *(const uint32_t*)(a16 + idx);
        float at0 = (float)(aa & 0xFFFFu) * (1.0f/32768.0f);
        float at1 = (float)(aa >> 16)     * (1.0f/32768.0f);
        __half2 uh = *(const __half2*)(u + idx);
        float u0 = __low2float(uh), u1 = __high2float(uh);
        B0 = at0 * B0 + (1.0f - at0) * u0; A0 *= at0;
        B1 = at1 * B1 + (1.0f - at1) * u1; A1 *= at1;
    }
    __shared__ float2 sA[32][32], sB[32][32], sP[32][32];
    sA[slice][tx] = make_float2(A0, A1);
    sB[slice][tx] = make_float2(B0, B1);
    __syncthreads();
    if (slice == 0){
        float2 carry = make_float2(0.0f, 0.0f);
#pragma unroll
        for (int s2 = 0; s2 < 32; s2++){
            sP[s2][tx] = carry;
            float2 a = sA[s2][tx], bb = sB[s2][tx];
            carry.x = a.x * carry.x + bb.x;
            carry.y = a.y * carry.y + bb.y;
        }
    }
    __syncthreads();
    float2 h = sP[slice][tx];
    idx = base + (size_t)t0 * DI;
    for (int t = 0; t < CH; t++, idx += DI){
        uint32_t aa = *(const uint32_t*)(a16 + idx);
        float at0 = (float)(aa & 0xFFFFu) * (1.0f/32768.0f);
        float at1 = (float)(aa >> 16)     * (1.0f/32768.0f);
        __half2 uh = *(const __half2*)(u + idx);
        h.x = at0 * h.x + (1.0f - at0) * __low2float(uh);
        h.y = at1 * h.y + (1.0f - at1) * __high2float(uh);
        float2 sz = *(const float2*)(spz + idx);
        __half2 yy = __floats2half2_rn(h.x * sz.x, h.y * sz.y);
        *(__half2*)(y + idx) = yy;
    }
}

// ---------------- launch ------------------------------------------------------
extern "C" void kernel_launch(void* const* d_in, const int* in_sizes, int n_in,
                              void* d_out, int out_size){
    const float* x     = (const float*)d_in[0];
    const float* gamma = (const float*)d_in[1];
    const float* step  = (const float*)d_in[2];
    const float* W_in  = (const float*)d_in[3];
    const float* cw    = (const float*)d_in[4];
    const float* cb    = (const float*)d_in[5];
    const float* W_x   = (const float*)d_in[6];
    const float* W_dt  = (const float*)d_in[7];
    const float* b_dt  = (const float*)d_in[8];
    const float* W_out = (const float*)d_in[9];
    float* out = (float*)d_out;

    __half *p_xn, *p_u, *p_dbl, *p_y, *p_tin, *p_tx, *p_tdt, *p_tout;
    float *p_xcraw, *p_spz, *p_scale, *p_part;
    unsigned short* p_decay;
    cudaGetSymbolAddress((void**)&p_xn,    g_xn);
    cudaGetSymbolAddress((void**)&p_xcraw, g_xcraw);
    cudaGetSymbolAddress((void**)&p_spz,   g_spz);
    cudaGetSymbolAddress((void**)&p_u,     g_u);
    cudaGetSymbolAddress((void**)&p_dbl,   g_dbl);
    cudaGetSymbolAddress((void**)&p_decay, g_decay16);
    cudaGetSymbolAddress((void**)&p_y,     g_y);
    cudaGetSymbolAddress((void**)&p_tin,   g_t_in);
    cudaGetSymbolAddress((void**)&p_tx,    g_t_x);
    cudaGetSymbolAddress((void**)&p_tdt,   g_t_dt);
    cudaGetSymbolAddress((void**)&p_tout,  g_t_out);
    cudaGetSymbolAddress((void**)&p_scale, g_scale);
    cudaGetSymbolAddress((void**)&p_part,  g_part);

    const int SM128 = 3*(128*RSG + 128*RSG)*2;   // 61440
    const int SM64  = 3*(128*RSG +  64*RSG)*2;   // 46080
    cudaFuncSetAttribute(k_gemm_h<128,4>, cudaFuncAttributeMaxDynamicSharedMemorySize, SM128);
    cudaFuncSetAttribute(k_gemm_h<64,3>,  cudaFuncAttributeMaxDynamicSharedMemorySize, SM64);
    cudaFuncSetAttribute(k_gemm_h<128,1>, cudaFuncAttributeMaxDynamicSharedMemorySize, SM128);
    cudaFuncSetAttribute(k_gemm_h<128,2>, cudaFuncAttributeMaxDynamicSharedMemorySize, SM128);

    // 1) ternary scales + exact-ternary fp16 weights (fused launches)
    k_abs4<<<dim3(256,4),256>>>(W_in, W_x, W_dt, W_out,
                                4096*1024/4, 96*2048/4, 2048*64/4, 1024*2048/4, p_part);
    k_absfin4<<<4,256>>>(p_part, 1.0f/4194304.0f, 1.0f/196608.0f,
                         1.0f/131072.0f, 1.0f/2097152.0f, p_scale);
    k_quant4<<<dim3(1024,4),256>>>(W_in, W_x, W_dt, W_out,
                                   p_tin, p_tx, p_tdt, p_tout,
                                   4194304/4, 131072/4, 131072/4, 2097152/4, p_scale);

    // 2) norm -> fp16
    k_norm<<<M_TOK,256>>>(x, gamma, step, p_xn);

    // 3) in-projection: split xc_raw (fp32) | squareplus(z) (fp32)
    k_gemm_h<128,4><<<dim3(32,64),256,SM128>>>(p_xn, p_tin, M_TOK, 4096, 1024,
                                               p_scale+0, nullptr, nullptr,
                                               p_xcraw, p_spz, nullptr, nullptr);

    // 4) causal conv + squareplus -> u fp16
    k_conv<<<M_TOK*DI/4/256,256>>>(p_xcraw, cw, cb, p_u);

    // 5) dt_rank projection -> dbl fp16
    k_gemm_h<64,3><<<dim3(1,64),256,SM64>>>(p_u, p_tx, M_TOK, 64, 2048,
                                            p_scale+1, nullptr, nullptr,
                                            nullptr, nullptr, p_dbl, nullptr);

    // 6) dt projection + fused sigmoid + dyadic round -> decay u16
    k_gemm_h<128,1><<<dim3(16,64),256,SM128>>>(p_dbl, p_tdt, M_TOK, 2048, 64,
                                               p_scale+2, b_dt, nullptr,
                                               nullptr, nullptr, nullptr, p_decay);

    // 7) scan + fused y = h * spz -> fp16
    k_scan<<<dim3(DI/64, BB), dim3(32,32)>>>(p_u, p_decay, p_spz, p_y);

    // 8) out-projection + residual -> d_out
    k_gemm_h<128,2><<<dim3(8,64),256,SM128>>>(p_y, p_tout, M_TOK, 1024, 2048,
                                              p_scale+3, nullptr, x,
                                              out, nullptr, nullptr, nullptr);
}

// round 8
// speedup vs baseline: 1.5975x; 1.0071x over previous
#include <cuda_runtime.h>
#include <cuda_fp16.h>
#include <math.h>
#include <stdint.h>

#define BB 4
#define LL 2048
#define DM 1024
#define DI 2048
#define DTR 64
#define M_TOK (BB*LL)           // 8192

// ---------------- scratch (device globals; allocation is forbidden) ----------
__device__ __align__(256) __half g_xn   [M_TOK * DM];
__device__ __align__(256) __half g_xcraw[M_TOK * DI];
__device__ __align__(256) __half g_spz  [M_TOK * DI];
__device__ __align__(256) __half g_u    [M_TOK * DI];
__device__ __align__(256) __half g_dbl  [M_TOK * DTR];
__device__ __align__(256) unsigned short g_decay16[M_TOK * DI];
__device__ __align__(256) __half g_y    [M_TOK * DI];
__device__ __align__(256) __half g_t_in [4096*1024];
__device__ __align__(256) __half g_t_x  [64*2048];
__device__ __align__(256) __half g_t_dt [2048*64];
__device__ __align__(256) __half g_t_out[1024*2048];
__device__ __align__(256) float  g_scale[4];
__device__ __align__(256) float  g_part [4*256];

// ---------------- exact reference math ---------------------------------------
__device__ __forceinline__ float squareplus_f(float x){
    float y = fminf(fmaxf(x*x + 4.0f, 1e-6f), 1e6f);
    float r = (y > 16.0f) ? 0.125f : 0.5f;
    if (y > 64.0f)  r = 0.0625f;
    if (y > 256.0f) r = 0.03125f;
    if (y < 4.0f)   r = 1.0f;
    if (y < 1.0f)   r = 2.0f;
    if (y < 0.25f)  r = 4.0f;
#pragma unroll
    for (int i = 0; i < 3; i++){
        r = r * (1.5f - 0.5f * y * r * r);
        r = fminf(fmaxf(r, 1e-6f), 1e3f);
    }
    float s = fminf(fmaxf(y * r, 0.0f), 1e3f);
    return 0.5f * (x + s);
}

__device__ __forceinline__ unsigned short decay_u16(float z){
    float sg = 0.5f + 0.5f * z / (1.0f + fabsf(z));
    return (unsigned short)(int)rintf(sg * 32768.0f);
}

// ---------------- fused weight scale + quant ----------------------------------
__global__ void k_abs4(const float* __restrict__ W0, const float* __restrict__ W1,
                       const float* __restrict__ W2, const float* __restrict__ W3,
                       int n0, int n1, int n2, int n3, float* __restrict__ partial){
    const float* W; int n;
    if      (blockIdx.y == 0){ W = W0; n = n0; }
    else if (blockIdx.y == 1){ W = W1; n = n1; }
    else if (blockIdx.y == 2){ W = W2; n = n2; }
    else                     { W = W3; n = n3; }
    __shared__ float sm[256];
    float s = 0.0f;
    for (int i = blockIdx.x * 256 + threadIdx.x; i < n; i += gridDim.x * 256){
        float4 v = ((const float4*)W)[i];
        s += fabsf(v.x) + fabsf(v.y) + fabsf(v.z) + fabsf(v.w);
    }
    sm[threadIdx.x] = s; __syncthreads();
    for (int o = 128; o > 0; o >>= 1){
        if (threadIdx.x < o) sm[threadIdx.x] += sm[threadIdx.x + o];
        __syncthreads();
    }
    if (threadIdx.x == 0) partial[blockIdx.y * 256 + blockIdx.x] = sm[0];
}

__global__ void k_absfin4(const float* __restrict__ partial, float i0, float i1,
                          float i2, float i3, float* __restrict__ out){
    __shared__ float sm[256];
    int b = blockIdx.x;
    float invn = (b == 0) ? i0 : (b == 1) ? i1 : (b == 2) ? i2 : i3;
    sm[threadIdx.x] = partial[b * 256 + threadIdx.x]; __syncthreads();
    for (int o = 128; o > 0; o >>= 1){
        if (threadIdx.x < o) sm[threadIdx.x] += sm[threadIdx.x + o];
        __syncthreads();
    }
    if (threadIdx.x == 0) out[b] = sm[0] * invn + 1e-8f;
}

__global__ void k_quant4(const float* __restrict__ W0, const float* __restrict__ W1,
                         const float* __restrict__ W2, const float* __restrict__ W3,
                         __half* __restrict__ T0, __half* __restrict__ T1,
                         __half* __restrict__ T2, __half* __restrict__ T3,
                         int n0, int n1, int n2, int n3,
                         const float* __restrict__ scale){
    const float* W; __half* T; int n;
    if      (blockIdx.y == 0){ W = W0; T = T0; n = n0; }
    else if (blockIdx.y == 1){ W = W1; T = T1; n = n1; }
    else if (blockIdx.y == 2){ W = W2; T = T2; n = n2; }
    else                     { W = W3; T = T3; n = n3; }
    float s = scale[blockIdx.y];
    for (int i = blockIdx.x * 256 + threadIdx.x; i < n; i += gridDim.x * 256){
        float4 v = ((const float4*)W)[i];
        float t0 = fminf(fmaxf(rintf(v.x / s), -1.0f), 1.0f);
        float t1 = fminf(fmaxf(rintf(v.y / s), -1.0f), 1.0f);
        float t2 = fminf(fmaxf(rintf(v.z / s), -1.0f), 1.0f);
        float t3 = fminf(fmaxf(rintf(v.w / s), -1.0f), 1.0f);
        __half2 p0 = __floats2half2_rn(t0, t1);
        __half2 p1 = __floats2half2_rn(t2, t3);
        uint2 u; u.x = *(uint32_t*)&p0; u.y = *(uint32_t*)&p1;
        ((uint2*)T)[i] = u;
    }
}

// ---------------- bitshift norm -> fp16 (shuffle reduction, fused sums) -------
__global__ void k_norm(const float* __restrict__ x, const float* __restrict__ gamma,
                       const float* __restrict__ step, __half* __restrict__ xn){
    __shared__ float sW[8], sW2[8];
    __shared__ float s_mean, s_g;
    int row = blockIdx.x;
    int tid = threadIdx.x, lane = tid & 31, w = tid >> 5;
    const float4* xr = (const float4*)(x + (size_t)row * DM);
    float4 v = xr[tid];
    float s1 = v.x + v.y + v.z + v.w;
    float s2 = v.x*v.x + v.y*v.y + v.z*v.z + v.w*v.w;
#pragma unroll
    for (int o = 16; o > 0; o >>= 1){
        s1 += __shfl_xor_sync(0xffffffffu, s1, o);
        s2 += __shfl_xor_sync(0xffffffffu, s2, o);
    }
    if (lane == 0){ sW[w] = s1; sW2[w] = s2; }
    __syncthreads();
    if (tid == 0){
        float t1 = 0.f, t2 = 0.f;
#pragma unroll
        for (int i = 0; i < 8; i++){ t1 += sW[i]; t2 += sW2[i]; }
        float mean = t1 * (1.0f / DM);
        float var = t2 * (1.0f / DM) - mean * mean;
        s_mean = mean;
        float vv = var + 1e-9f;
        float sc = 1.0f;
        if (vv >= 4.0f)     sc = 0.5f;
        if (vv >= 16.0f)    sc = 0.25f;
        if (vv >= 64.0f)    sc = 0.125f;
        if (vv >= 256.0f)   sc = 0.0625f;
        if (vv >= 1024.0f)  sc = 0.03125f;
        if (vv >= 4096.0f)  sc = 0.015625f;
        if (vv >= 16384.0f) sc = 0.0078125f;
        if (vv >= 65536.0f) sc = 0.00390625f;
        if (vv < 1.0f)      sc = 1.0f;
        if (vv < 0.25f)     sc = 2.0f;
        if (vv < 0.0625f)   sc = 4.0f;
        s_g = sc * step[0];
    }
    __syncthreads();
    float mean = s_mean, g = s_g;
    float4 gm = ((const float4*)gamma)[tid];
    __half2 p0 = __floats2half2_rn((v.x-mean)*g*gm.x, (v.y-mean)*g*gm.y);
    __half2 p1 = __floats2half2_rn((v.z-mean)*g*gm.z, (v.w-mean)*g*gm.w);
    uint2 uu; uu.x = *(uint32_t*)&p0; uu.y = *(uint32_t*)&p1;
    ((uint2*)xn)[ (size_t)row * (DM/4) + tid ] = uu;
}

// =================== MMA building blocks ======================================
#define RSG 40                    /* padded smem row stride (half elems) */

__device__ __forceinline__ void cp16(uint32_t saddr, const void* gptr){
    asm volatile("cp.async.cg.shared.global [%0],[%1],16;\n" :: "r"(saddr), "l"(gptr));
}
__device__ __forceinline__ void ldsm4(uint32_t* r, uint32_t a){
    asm volatile("ldmatrix.sync.aligned.m8n8.x4.shared.b16 {%0,%1,%2,%3},[%4];\n"
        : "=r"(r[0]), "=r"(r[1]), "=r"(r[2]), "=r"(r[3]) : "r"(a));
}
__device__ __forceinline__ void mma16816(float* c, const uint32_t* a, uint32_t b0, uint32_t b1){
    asm volatile(
        "mma.sync.aligned.m16n8k16.row.col.f32.f16.f16.f32 "
        "{%0,%1,%2,%3},{%4,%5,%6,%7},{%8,%9},{%0,%1,%2,%3};\n"
        : "+f"(c[0]), "+f"(c[1]), "+f"(c[2]), "+f"(c[3])
        : "r"(a[0]), "r"(a[1]), "r"(a[2]), "r"(a[3]), "r"(b0), "r"(b1));
}

// =================== single-A fp16 GEMM, 256 threads, BK=32, 3 stages ========
template<int BN>
__device__ __forceinline__ void ld_stage(uint32_t sbase, const __half* __restrict__ A,
                                         const __half* __restrict__ Bw,
                                         int m0, int n0, int K, int kb, int tid){
    constexpr int A_SZ = 128 * RSG;
#pragma unroll
    for (int j = 0; j < 2; j++){
        int idx = tid + j*256;
        int r = idx >> 2, sg = (idx & 3) * 8;
        cp16(sbase + (uint32_t)(r*RSG + sg)*2, A + (size_t)(m0 + r)*K + kb + sg);
    }
#pragma unroll
    for (int j = 0; j < BN*4/256; j++){
        int idx = tid + j*256;
        int r = idx >> 2, sg = (idx & 3) * 8;
        cp16(sbase + (uint32_t)(A_SZ + r*RSG + sg)*2, Bw + (size_t)(n0 + r)*K + kb + sg);
    }
    asm volatile("cp.async.commit_group;\n" ::);
}

// EPI: 1 decay->u16 | 2 +resid->C0f | 3 fp16 -> H0 | 4 split xcraw|spz (fp16)
template<int BN, int EPI>
__global__ __launch_bounds__(256, 2)
void k_gemm_h(const __half* __restrict__ A, const __half* __restrict__ Bw,
              int M, int N, int K,
              const float* __restrict__ scale_p,
              const float* __restrict__ bias,
              const float* __restrict__ resid,
              float* __restrict__ C0f,
              __half* __restrict__ H0, __half* __restrict__ H1,
              unsigned short* __restrict__ U16){
    constexpr int A_SZ = 128 * RSG;
    constexpr int B_SZ = BN * RSG;
    constexpr int STG  = A_SZ + B_SZ;
    constexpr int NG = BN / 32;
    constexpr int NT = BN / 16;
    extern __shared__ __align__(16) __half smem[];

    const int tid = threadIdx.x;
    const int m0 = blockIdx.y * 128, n0 = blockIdx.x * BN;
    const int lane = tid & 31, w = tid >> 5;
    const int wm = w >> 1, wn = w & 1;
    const int m0w = wm * 32, n0w = wn * (BN/2);

    float acc[2][NT][4];
#pragma unroll
    for (int i = 0; i < 2; i++)
#pragma unroll
        for (int j = 0; j < NT; j++)
#pragma unroll
            for (int q = 0; q < 4; q++) acc[i][j][q] = 0.0f;

    const int aoff = (m0w + (lane & 15)) * RSG + (lane >> 4) * 8;
    const int boff = (n0w + ((lane >> 4) << 3) + (lane & 7)) * RSG + ((lane >> 3) & 1) * 8;
    const int NITER = K / 32;
    uint32_t sb = (uint32_t)__cvta_generic_to_shared(smem);

    ld_stage<BN>(sb,         A, Bw, m0, n0, K, 0,  tid);
    ld_stage<BN>(sb + STG*2, A, Bw, m0, n0, K, 32, tid);

    for (int it = 0; it < NITER; it++){
        if (it + 1 < NITER) asm volatile("cp.async.wait_group 1;\n" ::);
        else                asm volatile("cp.async.wait_group 0;\n" ::);
        __syncthreads();
        if (it + 2 < NITER)
            ld_stage<BN>(sb + (uint32_t)(((it+2)%3)*STG)*2, A, Bw, m0, n0, K, (it+2)*32, tid);

        uint32_t sbase = sb + (uint32_t)((it%3)*STG)*2;
#pragma unroll
        for (int ks = 0; ks < 2; ks++){
            int ko = ks * 16;
            uint32_t ah0[4], ah1[4], bq[NG][4];
            ldsm4(ah0, sbase + (uint32_t)(aoff + ko)*2);
            ldsm4(ah1, sbase + (uint32_t)(aoff + 16*RSG + ko)*2);
#pragma unroll
            for (int j = 0; j < NG; j++)
                ldsm4(bq[j], sbase + (uint32_t)(A_SZ + boff + j*16*RSG + ko)*2);
#pragma unroll
            for (int j = 0; j < NG; j++){
                mma16816(acc[0][2*j],   ah0, bq[j][0], bq[j][1]);
                mma16816(acc[0][2*j+1], ah0, bq[j][2], bq[j][3]);
                mma16816(acc[1][2*j],   ah1, bq[j][0], bq[j][1]);
                mma16816(acc[1][2*j+1], ah1, bq[j][2], bq[j][3]);
            }
        }
    }

    float s = *scale_p;
#pragma unroll
    for (int mt = 0; mt < 2; mt++){
        int r0 = m0 + m0w + mt*16 + (lane >> 2);
        int r1 = r0 + 8;
#pragma unroll
        for (int nt = 0; nt < NT; nt++){
            int c = n0 + n0w + nt*8 + (lane & 3)*2;
            float v0 = acc[mt][nt][0]*s, v1 = acc[mt][nt][1]*s;
            float v2 = acc[mt][nt][2]*s, v3 = acc[mt][nt][3]*s;
            if (EPI == 1){
                U16[(size_t)r0*N + c]   = decay_u16(v0 + bias[c]);
                U16[(size_t)r0*N + c+1] = decay_u16(v1 + bias[c+1]);
                U16[(size_t)r1*N + c]   = decay_u16(v2 + bias[c]);
                U16[(size_t)r1*N + c+1] = decay_u16(v3 + bias[c+1]);
            } else if (EPI == 2){
                C0f[(size_t)r0*N + c]   = v0 + resid[(size_t)r0*N + c];
                C0f[(size_t)r0*N + c+1] = v1 + resid[(size_t)r0*N + c+1];
                C0f[(size_t)r1*N + c]   = v2 + resid[(size_t)r1*N + c];
                C0f[(size_t)r1*N + c+1] = v3 + resid[(size_t)r1*N + c+1];
            } else if (EPI == 3){
                __half2 p0 = __floats2half2_rn(v0, v1);
                __half2 p1 = __floats2half2_rn(v2, v3);
                *(uint32_t*)&H0[(size_t)r0*N + c] = *(uint32_t*)&p0;
                *(uint32_t*)&H0[(size_t)r1*N + c] = *(uint32_t*)&p1;
            } else {  // EPI == 4: xcraw (fp16) | spz = squareplus (fp16)
                if (c < DI){
                    __half2 p0 = __floats2half2_rn(v0, v1);
                    __half2 p1 = __floats2half2_rn(v2, v3);
                    *(uint32_t*)&H0[(size_t)r0*DI + c] = *(uint32_t*)&p0;
                    *(uint32_t*)&H0[(size_t)r1*DI + c] = *(uint32_t*)&p1;
                } else {
                    int cc = c - DI;
                    __half2 p0 = __floats2half2_rn(squareplus_f(v0), squareplus_f(v1));
                    __half2 p1 = __floats2half2_rn(squareplus_f(v2), squareplus_f(v3));
                    *(uint32_t*)&H1[(size_t)r0*DI + cc] = *(uint32_t*)&p0;
                    *(uint32_t*)&H1[(size_t)r1*DI + cc] = *(uint32_t*)&p1;
                }
            }
        }
    }
}

// ---------------- causal depthwise conv1d(k=4) + squareplus (8ch/thread) -----
__global__ void k_conv(const __half* __restrict__ xcraw, const float* __restrict__ cw,
                       const float* __restrict__ cb, __half* __restrict__ u){
    int i = blockIdx.x * 256 + threadIdx.x;      // over total/8
    int idx = i * 8;
    int d0 = idx & (DI - 1);
    int m = idx >> 11;
    int t = m & (LL - 1);
    const uint4* x8 = (const uint4*)xcraw;
    uint4 z4 = make_uint4(0u,0u,0u,0u);
    uint4 q0 = x8[i];
    uint4 q1 = (t >= 1) ? x8[i - DI/8]   : z4;
    uint4 q2 = (t >= 2) ? x8[i - 2*DI/8] : z4;
    uint4 q3 = (t >= 3) ? x8[i - 3*DI/8] : z4;
    const __half2* h0 = (const __half2*)&q0;
    const __half2* h1 = (const __half2*)&q1;
    const __half2* h2 = (const __half2*)&q2;
    const __half2* h3 = (const __half2*)&q3;
    uint4 outv;
    __half2* ov = (__half2*)&outv;
#pragma unroll
    for (int p = 0; p < 4; p++){
        int da = d0 + p*2, db = da + 1;
        float4 wA = ((const float4*)cw)[da];
        float4 wB = ((const float4*)cw)[db];
        float2 cb2 = ((const float2*)cb)[(d0 >> 1) + p];
        float xa0 = __low2float(h0[p]),  xb0 = __high2float(h0[p]);
        float xa1 = __low2float(h1[p]),  xb1 = __high2float(h1[p]);
        float xa2 = __low2float(h2[p]),  xb2 = __high2float(h2[p]);
        float xa3 = __low2float(h3[p]),  xb3 = __high2float(h3[p]);
        float sa = cb2.x + wA.w*xa0 + wA.z*xa1 + wA.y*xa2 + wA.x*xa3;
        float sbv = cb2.y + wB.w*xb0 + wB.z*xb1 + wB.y*xb2 + wB.x*xb3;
        ov[p] = __floats2half2_rn(squareplus_f(sa), squareplus_f(sbv));
    }
    ((uint4*)u)[i] = outv;
}

// ---------------- chunked scan, 2 channels/thread, 32 slices x 64 ------------
__global__ void k_scan(const __half* __restrict__ u,
                       const unsigned short* __restrict__ a16,
                       const __half* __restrict__ spz,
                       __half* __restrict__ y){
    const int tx = threadIdx.x;
    const int c0 = (blockIdx.x * 32 + tx) * 2;
    const int b = blockIdx.y;
    const int slice = threadIdx.y;
    const int CH = LL / 32;                        // 64
    size_t base = ((size_t)b * LL) * DI + c0;
    int t0 = slice * CH;

    float A0 = 1.0f, B0 = 0.0f, A1 = 1.0f, B1 = 0.0f;
    size_t idx = base + (size_t)t0 * DI;
    for (int t = 0; t < CH; t++, idx += DI){
        uint32_t aa = *(const uint32_t*)(a16 + idx);
        float at0 = (float)(aa & 0xFFFFu) * (1.0f/32768.0f);
        float at1 = (float)(aa >> 16)     * (1.0f/32768.0f);
        __half2 uh = *(const __half2*)(u + idx);
        float u0 = __low2float(uh), u1 = __high2float(uh);
        B0 = at0 * B0 + (1.0f - at0) * u0; A0 *= at0;
        B1 = at1 * B1 + (1.0f - at1) * u1; A1 *= at1;
    }
    __shared__ float2 sA[32][32], sB[32][32], sP[32][32];
    sA[slice][tx] = make_float2(A0, A1);
    sB[slice][tx] = make_float2(B0, B1);
    __syncthreads();
    if (slice == 0){
        float2 carry = make_float2(0.0f, 0.0f);
#pragma unroll
        for (int s2 = 0; s2 < 32; s2++){
            sP[s2][tx] = carry;
            float2 a = sA[s2][tx], bb = sB[s2][tx];
            carry.x = a.x * carry.x + bb.x;
            carry.y = a.y * carry.y + bb.y;
        }
    }
    __syncthreads();
    float2 h = sP[slice][tx];
    idx = base + (size_t)t0 * DI;
    for (int t = 0; t < CH; t++, idx += DI){
        uint32_t aa = *(const uint32_t*)(a16 + idx);
        float at0 = (float)(aa & 0xFFFFu) * (1.0f/32768.0f);
        float at1 = (float)(aa >> 16)     * (1.0f/32768.0f);
        __half2 uh = *(const __half2*)(u + idx);
        h.x = at0 * h.x + (1.0f - at0) * __low2float(uh);
        h.y = at1 * h.y + (1.0f - at1) * __high2float(uh);
        __half2 sz = *(const __half2*)(spz + idx);
        __half2 yy = __floats2half2_rn(h.x * __low2float(sz), h.y * __high2float(sz));
        *(__half2*)(y + idx) = yy;
    }
}

// ---------------- launch ------------------------------------------------------
extern "C" void kernel_launch(void* const* d_in, const int* in_sizes, int n_in,
                              void* d_out, int out_size){
    const float* x     = (const float*)d_in[0];
    const float* gamma = (const float*)d_in[1];
    const float* step  = (const float*)d_in[2];
    const float* W_in  = (const float*)d_in[3];
    const float* cw    = (const float*)d_in[4];
    const float* cb    = (const float*)d_in[5];
    const float* W_x   = (const float*)d_in[6];
    const float* W_dt  = (const float*)d_in[7];
    const float* b_dt  = (const float*)d_in[8];
    const float* W_out = (const float*)d_in[9];
    float* out = (float*)d_out;

    __half *p_xn, *p_xcraw, *p_spz, *p_u, *p_dbl, *p_y;
    __half *p_tin, *p_tx, *p_tdt, *p_tout;
    float *p_scale, *p_part;
    unsigned short* p_decay;
    cudaGetSymbolAddress((void**)&p_xn,    g_xn);
    cudaGetSymbolAddress((void**)&p_xcraw, g_xcraw);
    cudaGetSymbolAddress((void**)&p_spz,   g_spz);
    cudaGetSymbolAddress((void**)&p_u,     g_u);
    cudaGetSymbolAddress((void**)&p_dbl,   g_dbl);
    cudaGetSymbolAddress((void**)&p_decay, g_decay16);
    cudaGetSymbolAddress((void**)&p_y,     g_y);
    cudaGetSymbolAddress((void**)&p_tin,   g_t_in);
    cudaGetSymbolAddress((void**)&p_tx,    g_t_x);
    cudaGetSymbolAddress((void**)&p_tdt,   g_t_dt);
    cudaGetSymbolAddress((void**)&p_tout,  g_t_out);
    cudaGetSymbolAddress((void**)&p_scale, g_scale);
    cudaGetSymbolAddress((void**)&p_part,  g_part);

    const int SM128 = 3*(128*RSG + 128*RSG)*2;   // 61440
    const int SM64  = 3*(128*RSG +  64*RSG)*2;   // 46080
    cudaFuncSetAttribute(k_gemm_h<128,4>, cudaFuncAttributeMaxDynamicSharedMemorySize, SM128);
    cudaFuncSetAttribute(k_gemm_h<64,3>,  cudaFuncAttributeMaxDynamicSharedMemorySize, SM64);
    cudaFuncSetAttribute(k_gemm_h<128,1>, cudaFuncAttributeMaxDynamicSharedMemorySize, SM128);
    cudaFuncSetAttribute(k_gemm_h<128,2>, cudaFuncAttributeMaxDynamicSharedMemorySize, SM128);

    // 1) ternary scales + exact-ternary fp16 weights (fused launches)
    k_abs4<<<dim3(256,4),256>>>(W_in, W_x, W_dt, W_out,
                                4096*1024/4, 96*2048/4, 2048*64/4, 1024*2048/4, p_part);
    k_absfin4<<<4,256>>>(p_part, 1.0f/4194304.0f, 1.0f/196608.0f,
                         1.0f/131072.0f, 1.0f/2097152.0f, p_scale);
    k_quant4<<<dim3(1024,4),256>>>(W_in, W_x, W_dt, W_out,
                                   p_tin, p_tx, p_tdt, p_tout,
                                   4194304/4, 131072/4, 131072/4, 2097152/4, p_scale);

    // 2) norm -> fp16
    k_norm<<<M_TOK,256>>>(x, gamma, step, p_xn);

    // 3) in-projection: split xc_raw (fp16) | squareplus(z) (fp16)
    k_gemm_h<128,4><<<dim3(32,64),256,SM128>>>(p_xn, p_tin, M_TOK, 4096, 1024,
                                               p_scale+0, nullptr, nullptr,
                                               nullptr, p_xcraw, p_spz, nullptr);

    // 4) causal conv + squareplus -> u fp16 (8 channels per thread)
    k_conv<<<M_TOK*DI/8/256,256>>>(p_xcraw, cw, cb, p_u);

    // 5) dt_rank projection -> dbl fp16
    k_gemm_h<64,3><<<dim3(1,64),256,SM64>>>(p_u, p_tx, M_TOK, 64, 2048,
                                            p_scale+1, nullptr, nullptr,
                                            nullptr, p_dbl, nullptr, nullptr);

    // 6) dt projection + fused sigmoid + dyadic round -> decay u16
    k_gemm_h<128,1><<<dim3(16,64),256,SM128>>>(p_dbl, p_tdt, M_TOK, 2048, 64,
                                               p_scale+2, b_dt, nullptr,
                                               nullptr, nullptr, nullptr, p_decay);

    // 7) scan + fused y = h * spz -> fp16
    k_scan<<<dim3(DI/64, BB), dim3(32,32)>>>(p_u, p_decay, p_spz, p_y);

    // 8) out-projection + residual -> d_out (fp32)
    k_gemm_h<128,2><<<dim3(8,64),256,SM128>>>(p_y, p_tout, M_TOK, 1024, 2048,
                                              p_scale+3, nullptr, x,
                                              out, nullptr, nullptr, nullptr);
}